// round 1
// baseline (speedup 1.0000x reference)
#include <cuda_runtime.h>

// Problem dims
#define BZc   8
#define NUMc  1024
#define NAc   64
#define FDc   128

typedef unsigned long long u64;

// ---------------- packed f32x2 helpers (sm_100+ PTX) ----------------
__device__ __forceinline__ u64 pk2(float a, float b) {
    u64 r; asm("mov.b64 %0, {%1,%2};" : "=l"(r) : "f"(a), "f"(b)); return r;
}
__device__ __forceinline__ void upk2(u64 v, float& a, float& b) {
    asm("mov.b64 {%0,%1}, %2;" : "=f"(a), "=f"(b) : "l"(v));
}
__device__ __forceinline__ u64 ffma2(u64 a, u64 b, u64 c) {
    u64 d; asm("fma.rn.f32x2 %0, %1, %2, %3;" : "=l"(d) : "l"(a), "l"(b), "l"(c)); return d;
}

// ---------------- folded weight storage (device globals, no allocation) ----
__device__ u64   g_A1[FDc][32];   // [c][j] = (s1[2j]*Wf1[2j][c], s1[2j+1]*Wf1[2j+1][c])
__device__ float g_c1[64];        // folded bias+BN of feature layer 1
__device__ u64   g_Mf[64][16];    // [h][q] = folded (ga/sqrt)*Wa1_f@Wf2, pairs over o
__device__ u64   g_Ms[16][16];    // [n][q] = folded (ga/sqrt)*Wa1_s@Ws3, pairs over o
__device__ float g_ca[32];        // folded constant into agg layer pre-tanh
__device__ float g_B1[8][4];      // spatial layer1 folded (padded row)
__device__ float g_d1[8];
__device__ float g_B2[16][8];     // spatial layer2 folded
__device__ float g_d2[16];
__device__ float g_Wa2[32];
__device__ float g_ba2s;

// ---------------- weight folding kernel ----------------
__global__ void disarm_prep(
    const float* __restrict__ Wf1, const float* __restrict__ bf1,
    const float* __restrict__ gf1, const float* __restrict__ btf1,
    const float* __restrict__ Wf2, const float* __restrict__ bf2,
    const float* __restrict__ Ws1, const float* __restrict__ bs1,
    const float* __restrict__ gs1, const float* __restrict__ bts1,
    const float* __restrict__ Ws2, const float* __restrict__ bs2,
    const float* __restrict__ gs2, const float* __restrict__ bts2,
    const float* __restrict__ Ws3, const float* __restrict__ bs3,
    const float* __restrict__ Wa1, const float* __restrict__ ba1,
    const float* __restrict__ ga1, const float* __restrict__ bta1,
    const float* __restrict__ Wa2, const float* __restrict__ ba2)
{
    const float inv = rsqrtf(1.0f + 1e-5f);
    const int t = threadIdx.x;
    const int nt = blockDim.x;

    // A1 packed: pairs over output channel o
    for (int i = t; i < FDc * 32; i += nt) {
        int c = i >> 5, j = i & 31;
        float a = gf1[2*j]   * inv * Wf1[(2*j)  * FDc + c];
        float b = gf1[2*j+1] * inv * Wf1[(2*j+1)* FDc + c];
        g_A1[c][j] = pk2(a, b);
    }
    for (int i = t; i < 64; i += nt) g_c1[i] = gf1[i]*inv*bf1[i] + btf1[i];

    // Mf[h][q]: o = 2q, 2q+1 : ga1[o]*inv * sum_k Wa1[o][32+k]*Wf2[k][h]
    for (int i = t; i < 64 * 16; i += nt) {
        int h = i >> 4, q = i & 15;
        float v[2];
        #pragma unroll
        for (int s = 0; s < 2; ++s) {
            int o = 2*q + s;
            float acc = 0.0f;
            for (int k = 0; k < 32; ++k) acc += Wa1[o*64 + 32 + k] * Wf2[k*64 + h];
            v[s] = ga1[o] * inv * acc;
        }
        g_Mf[h][q] = pk2(v[0], v[1]);
    }
    // Ms[n][q]: o = 2q, 2q+1 : ga1[o]*inv * sum_m Wa1[o][m]*Ws3[m][n]
    for (int i = t; i < 16 * 16; i += nt) {
        int n = i >> 4, q = i & 15;
        float v[2];
        #pragma unroll
        for (int s = 0; s < 2; ++s) {
            int o = 2*q + s;
            float acc = 0.0f;
            for (int m = 0; m < 32; ++m) acc += Wa1[o*64 + m] * Ws3[m*16 + n];
            v[s] = ga1[o] * inv * acc;
        }
        g_Ms[n][q] = pk2(v[0], v[1]);
    }
    if (t < 32) {
        float acc = 0.0f;
        for (int k = 0; k < 32; ++k) acc += Wa1[t*64 + 32 + k] * bf2[k];
        for (int m = 0; m < 32; ++m) acc += Wa1[t*64 + m] * bs3[m];
        g_ca[t] = ga1[t]*inv*(acc + ba1[t]) + bta1[t];
    }
    if (t < 8) {
        for (int i = 0; i < 3; ++i) g_B1[t][i] = gs1[t]*inv*Ws1[t*3 + i];
        g_B1[t][3] = 0.0f;
        g_d1[t] = gs1[t]*inv*bs1[t] + bts1[t];
    }
    if (t < 16) {
        for (int i = 0; i < 8; ++i) g_B2[t][i] = gs2[t]*inv*Ws2[t*8 + i];
        g_d2[t] = gs2[t]*inv*bs2[t] + bts2[t];
    }
    if (t < 32) g_Wa2[t] = Wa2[t];
    if (t == 0) g_ba2s = ba2[0];
}

// ---------------- main fused kernel ----------------
// 256 threads = 4 groups of 64; each group = one (b,p), one thread per anchor.
__global__ void __launch_bounds__(256) disarm_main(
    const float* __restrict__ loc, const float* __restrict__ feat,
    float* __restrict__ out)
{
    __shared__ ulonglong2 sW[FDc][16];   // 32 KB : layer-1 weight pairs
    __shared__ ulonglong2 sMf[64][8];    //  8 KB
    __shared__ ulonglong2 sMs[16][8];    //  2 KB
    __shared__ float sc1[64], sca[32], sWa2v[32];
    __shared__ float sB1[8][4], sd1[8], sB2[16][8], sd2[16];
    __shared__ float sba2;
    __shared__ float rmx[4][2], rmn[4][2], rsum[4][2];

    const int tid = threadIdx.x;

    // stage folded weights into shared
    {
        u64* d = (u64*)&sW[0][0]; const u64* s = &g_A1[0][0];
        for (int i = tid; i < FDc*32; i += 256) d[i] = s[i];
        u64* d2 = (u64*)&sMf[0][0]; const u64* s2 = &g_Mf[0][0];
        for (int i = tid; i < 64*16; i += 256) d2[i] = s2[i];
        u64* d3 = (u64*)&sMs[0][0]; const u64* s3 = &g_Ms[0][0];
        d3[tid] = s3[tid];  // exactly 256 elements
        if (tid < 64) sc1[tid] = g_c1[tid];
        if (tid < 32) { sca[tid] = g_ca[tid]; sWa2v[tid] = g_Wa2[tid]; }
        if (tid < 32) sB1[tid>>2][tid&3] = g_B1[tid>>2][tid&3];
        if (tid < 8)  sd1[tid] = g_d1[tid];
        if (tid < 128) sB2[tid>>3][tid&7] = g_B2[tid>>3][tid&7];
        if (tid < 16) sd2[tid] = g_d2[tid];
        if (tid == 0) sba2 = g_ba2s;
    }
    __syncthreads();

    const int grp = tid >> 6;
    const int gt  = tid & 63;           // anchor index
    const int gp  = blockIdx.x * 4 + grp;
    const int b   = gp >> 10;
    const int p   = gp & 1023;

    // ---- spatial branch: 3 -> 8 -> 16 (tanh each) ----
    const float* lp = loc + (((size_t)(b*NUMc + p))*NAc + gt) * 3;
    const float l0 = lp[0], l1 = lp[1], l2 = lp[2];
    float s1v[8];
    #pragma unroll
    for (int j = 0; j < 8; ++j)
        s1v[j] = tanhf(sB1[j][0]*l0 + sB1[j][1]*l1 + sB1[j][2]*l2 + sd1[j]);
    float s2v[16];
    #pragma unroll
    for (int j = 0; j < 16; ++j) {
        float a = sd2[j];
        #pragma unroll
        for (int i = 0; i < 8; ++i) a += sB2[j][i] * s1v[i];
        s2v[j] = tanhf(a);
    }

    // ---- feature layer 1: h_pre[64] = A1 @ x + c1 (packed pairs) ----
    u64 acc[32];
    #pragma unroll
    for (int j = 0; j < 32; ++j) acc[j] = pk2(sc1[2*j], sc1[2*j+1]);

    const size_t cs = (size_t)NUMc * NAc;            // 65536
    const float* fb = feat + (size_t)b * FDc * cs + (size_t)p * NAc + gt;

    float x0 = __ldg(fb);
    float x1 = __ldg(fb + cs);
    float x2 = __ldg(fb + 2*cs);
    float x3 = __ldg(fb + 3*cs);

    for (int c0 = 0; c0 < FDc; c0 += 4) {
        float n0 = 0.f, n1 = 0.f, n2 = 0.f, n3 = 0.f;
        if (c0 + 4 < FDc) {
            const float* nb = fb + (size_t)(c0 + 4) * cs;
            n0 = __ldg(nb); n1 = __ldg(nb + cs); n2 = __ldg(nb + 2*cs); n3 = __ldg(nb + 3*cs);
        }
        u64 xx;
        xx = pk2(x0, x0);
        #pragma unroll
        for (int j2 = 0; j2 < 16; ++j2) {
            ulonglong2 w = sW[c0][j2];
            acc[2*j2]   = ffma2(w.x, xx, acc[2*j2]);
            acc[2*j2+1] = ffma2(w.y, xx, acc[2*j2+1]);
        }
        xx = pk2(x1, x1);
        #pragma unroll
        for (int j2 = 0; j2 < 16; ++j2) {
            ulonglong2 w = sW[c0+1][j2];
            acc[2*j2]   = ffma2(w.x, xx, acc[2*j2]);
            acc[2*j2+1] = ffma2(w.y, xx, acc[2*j2+1]);
        }
        xx = pk2(x2, x2);
        #pragma unroll
        for (int j2 = 0; j2 < 16; ++j2) {
            ulonglong2 w = sW[c0+2][j2];
            acc[2*j2]   = ffma2(w.x, xx, acc[2*j2]);
            acc[2*j2+1] = ffma2(w.y, xx, acc[2*j2+1]);
        }
        xx = pk2(x3, x3);
        #pragma unroll
        for (int j2 = 0; j2 < 16; ++j2) {
            ulonglong2 w = sW[c0+3][j2];
            acc[2*j2]   = ffma2(w.x, xx, acc[2*j2]);
            acc[2*j2+1] = ffma2(w.y, xx, acc[2*j2+1]);
        }
        x0 = n0; x1 = n1; x2 = n2; x3 = n3;
    }

    // ---- aggregated layer pre-activation: a2 = Ms@s2 + Mf@tanh(h_pre) + ca ----
    u64 a2[16];
    #pragma unroll
    for (int q = 0; q < 16; ++q) a2[q] = pk2(sca[2*q], sca[2*q+1]);

    #pragma unroll
    for (int n = 0; n < 16; ++n) {
        u64 xx = pk2(s2v[n], s2v[n]);
        #pragma unroll
        for (int q2 = 0; q2 < 8; ++q2) {
            ulonglong2 w = sMs[n][q2];
            a2[2*q2]   = ffma2(w.x, xx, a2[2*q2]);
            a2[2*q2+1] = ffma2(w.y, xx, a2[2*q2+1]);
        }
    }

    #pragma unroll
    for (int j = 0; j < 32; ++j) {
        float ha, hb; upk2(acc[j], ha, hb);
        ha = tanhf(ha); hb = tanhf(hb);
        const u64 xa = pk2(ha, ha);
        const u64 xb = pk2(hb, hb);
        #pragma unroll
        for (int q2 = 0; q2 < 8; ++q2) {
            ulonglong2 wA = sMf[2*j][q2];
            a2[2*q2]   = ffma2(wA.x, xa, a2[2*q2]);
            a2[2*q2+1] = ffma2(wA.y, xa, a2[2*q2+1]);
        }
        #pragma unroll
        for (int q2 = 0; q2 < 8; ++q2) {
            ulonglong2 wB = sMf[2*j+1][q2];
            a2[2*q2]   = ffma2(wB.x, xb, a2[2*q2]);
            a2[2*q2+1] = ffma2(wB.y, xb, a2[2*q2+1]);
        }
    }

    // ---- scalar head: out = Wa2 @ tanh(a2) + ba2; logit = tanh(out) ----
    float outv = sba2;
    #pragma unroll
    for (int q = 0; q < 16; ++q) {
        float a, bb; upk2(a2[q], a, bb);
        outv += sWa2v[2*q] * tanhf(a) + sWa2v[2*q+1] * tanhf(bb);
    }
    const float lg = tanhf(outv);

    // ---- softmax over 64 anchors (2 warps per group) + min-max norm ----
    const unsigned m32 = 0xffffffffu;
    float mx = lg, mn = lg;
    #pragma unroll
    for (int off = 16; off > 0; off >>= 1) {
        mx = fmaxf(mx, __shfl_xor_sync(m32, mx, off));
        mn = fminf(mn, __shfl_xor_sync(m32, mn, off));
    }
    const int half = gt >> 5;
    if ((gt & 31) == 0) { rmx[grp][half] = mx; rmn[grp][half] = mn; }
    __syncthreads();
    mx = fmaxf(rmx[grp][0], rmx[grp][1]);
    mn = fminf(rmn[grp][0], rmn[grp][1]);

    const float e = expf(lg - mx);
    float s = e;
    #pragma unroll
    for (int off = 16; off > 0; off >>= 1) s += __shfl_xor_sync(m32, s, off);
    if ((gt & 31) == 0) rsum[grp][half] = s;
    __syncthreads();
    const float sum  = rsum[grp][0] + rsum[grp][1];
    const float invs = 1.0f / sum;

    const float w   = e * invs;
    const float wmn = expf(mn - mx) * invs;  // min over anchors of w
    const float wmx = invs;                  // max: exp(0)/sum
    const float k   = (1.0f + 1e-6f) / (wmx - wmn + 1e-6f);
    const float wn  = k * (w - wmn);

    const size_t oi = (size_t)gp * NAc + gt;
    out[oi] = w;
    out[(size_t)BZc * NUMc * NAc + oi] = wn;
}

// ---------------- launch ----------------
extern "C" void kernel_launch(void* const* d_in, const int* in_sizes, int n_in,
                              void* d_out, int out_size)
{
    const float* loc  = (const float*)d_in[0];
    const float* feat = (const float*)d_in[1];

    disarm_prep<<<1, 256>>>(
        (const float*)d_in[2],  (const float*)d_in[3],  (const float*)d_in[4],  (const float*)d_in[5],
        (const float*)d_in[6],  (const float*)d_in[7],
        (const float*)d_in[8],  (const float*)d_in[9],  (const float*)d_in[10], (const float*)d_in[11],
        (const float*)d_in[12], (const float*)d_in[13], (const float*)d_in[14], (const float*)d_in[15],
        (const float*)d_in[16], (const float*)d_in[17],
        (const float*)d_in[18], (const float*)d_in[19], (const float*)d_in[20], (const float*)d_in[21],
        (const float*)d_in[22], (const float*)d_in[23]);

    disarm_main<<<(BZc * NUMc) / 4, 256>>>(loc, feat, (float*)d_out);
}

// round 2
// speedup vs baseline: 1.1792x; 1.1792x over previous
#include <cuda_runtime.h>

// Problem dims
#define BZc   8
#define NUMc  1024
#define NAc   64
#define FDc   128

typedef unsigned long long u64;

// ---------------- packed f32x2 helpers (sm_100+ PTX) ----------------
__device__ __forceinline__ u64 pk2(float a, float b) {
    u64 r; asm("mov.b64 %0, {%1,%2};" : "=l"(r) : "f"(a), "f"(b)); return r;
}
__device__ __forceinline__ void upk2(u64 v, float& a, float& b) {
    asm("mov.b64 {%0,%1}, %2;" : "=f"(a), "=f"(b) : "l"(v));
}
__device__ __forceinline__ u64 ffma2(u64 a, u64 b, u64 c) {
    u64 d; asm("fma.rn.f32x2 %0, %1, %2, %3;" : "=l"(d) : "l"(a), "l"(b), "l"(c)); return d;
}
// HW tanh approx (1 MUFU op). Used for HIDDEN activations only; error is
// attenuated by the folded Mf/Ms weights (~1e-2 scale) before the logit.
__device__ __forceinline__ float tanha(float x) {
    float y; asm("tanh.approx.f32 %0, %1;" : "=f"(y) : "f"(x)); return y;
}

// ---------------- folded weight storage (device globals) ----------------
// Layer-1 weights, pass-major: pass p covers outputs [32p, 32p+32).
// g_W[p][c][j] packs outputs (32p+2j, 32p+2j+1) for channel c.
__device__ u64   g_W[2][FDc][16];
__device__ float g_c1[64];        // folded bias+BN of feature layer 1
__device__ u64   g_Mf[64][16];    // folded (ga/s)*Wa1_f@Wf2, pairs over o
__device__ u64   g_Ms[16][16];    // folded (ga/s)*Wa1_s@Ws3, pairs over o
__device__ float g_ca[32];        // folded constant into agg pre-tanh
__device__ float g_B1[8][4];
__device__ float g_d1[8];
__device__ float g_B2[16][8];
__device__ float g_d2[16];
__device__ float g_Wa2[32];
__device__ float g_ba2s;

// ---------------- weight folding kernel ----------------
__global__ void disarm_prep(
    const float* __restrict__ Wf1, const float* __restrict__ bf1,
    const float* __restrict__ gf1, const float* __restrict__ btf1,
    const float* __restrict__ Wf2, const float* __restrict__ bf2,
    const float* __restrict__ Ws1, const float* __restrict__ bs1,
    const float* __restrict__ gs1, const float* __restrict__ bts1,
    const float* __restrict__ Ws2, const float* __restrict__ bs2,
    const float* __restrict__ gs2, const float* __restrict__ bts2,
    const float* __restrict__ Ws3, const float* __restrict__ bs3,
    const float* __restrict__ Wa1, const float* __restrict__ ba1,
    const float* __restrict__ ga1, const float* __restrict__ bta1,
    const float* __restrict__ Wa2, const float* __restrict__ ba2)
{
    const float inv = rsqrtf(1.0f + 1e-5f);
    const int t = threadIdx.x;
    const int nt = blockDim.x;

    // Layer-1 pairs, pass-major
    for (int i = t; i < 2 * FDc * 16; i += nt) {
        int p = i / (FDc * 16);
        int c = (i >> 4) & (FDc - 1);
        int j = i & 15;
        int o0 = 32 * p + 2 * j;
        float a = gf1[o0]   * inv * Wf1[o0 * FDc + c];
        float b = gf1[o0+1] * inv * Wf1[(o0+1) * FDc + c];
        g_W[p][c][j] = pk2(a, b);
    }
    for (int i = t; i < 64; i += nt) g_c1[i] = gf1[i]*inv*bf1[i] + btf1[i];

    // Mf[h][q]: o = 2q, 2q+1 : ga1[o]*inv * sum_k Wa1[o][32+k]*Wf2[k][h]
    for (int i = t; i < 64 * 16; i += nt) {
        int h = i >> 4, q = i & 15;
        float v[2];
        #pragma unroll
        for (int s = 0; s < 2; ++s) {
            int o = 2*q + s;
            float acc = 0.0f;
            for (int k = 0; k < 32; ++k) acc += Wa1[o*64 + 32 + k] * Wf2[k*64 + h];
            v[s] = ga1[o] * inv * acc;
        }
        g_Mf[h][q] = pk2(v[0], v[1]);
    }
    // Ms[n][q]
    for (int i = t; i < 16 * 16; i += nt) {
        int n = i >> 4, q = i & 15;
        float v[2];
        #pragma unroll
        for (int s = 0; s < 2; ++s) {
            int o = 2*q + s;
            float acc = 0.0f;
            for (int m = 0; m < 32; ++m) acc += Wa1[o*64 + m] * Ws3[m*16 + n];
            v[s] = ga1[o] * inv * acc;
        }
        g_Ms[n][q] = pk2(v[0], v[1]);
    }
    if (t < 32) {
        float acc = 0.0f;
        for (int k = 0; k < 32; ++k) acc += Wa1[t*64 + 32 + k] * bf2[k];
        for (int m = 0; m < 32; ++m) acc += Wa1[t*64 + m] * bs3[m];
        g_ca[t] = ga1[t]*inv*(acc + ba1[t]) + bta1[t];
    }
    if (t < 8) {
        for (int i = 0; i < 3; ++i) g_B1[t][i] = gs1[t]*inv*Ws1[t*3 + i];
        g_B1[t][3] = 0.0f;
        g_d1[t] = gs1[t]*inv*bs1[t] + bts1[t];
    }
    if (t < 16) {
        for (int i = 0; i < 8; ++i) g_B2[t][i] = gs2[t]*inv*Ws2[t*8 + i];
        g_d2[t] = gs2[t]*inv*bs2[t] + bts2[t];
    }
    if (t < 32) g_Wa2[t] = Wa2[t];
    if (t == 0) g_ba2s = ba2[0];
}

// ---------------- one 32-output half-matvec pass ----------------
// Computes acc (16 packed pairs) over all 128 channels, tanh's the results,
// and folds them into a2 via the Mf rows for this half.
__device__ __forceinline__ void half_pass(
    const ulonglong2* __restrict__ wp,      // sW[pass][0][0], 8 ulonglong2/channel
    const ulonglong2 (* __restrict__ sMf)[8],
    const float* __restrict__ sc1,          // +32*pass already applied
    const float* __restrict__ fb,           // feature base for this (b,p,anchor)
    size_t cs, u64* a2)
{
    u64 acc[16];
    #pragma unroll
    for (int j = 0; j < 16; ++j) acc[j] = pk2(sc1[2*j], sc1[2*j+1]);

    float x0 = __ldg(fb);
    float x1 = __ldg(fb + cs);
    float x2 = __ldg(fb + 2*cs);
    float x3 = __ldg(fb + 3*cs);

    for (int c0 = 0; c0 < FDc; c0 += 4) {
        float n0 = 0.f, n1 = 0.f, n2 = 0.f, n3 = 0.f;
        if (c0 + 4 < FDc) {
            const float* nb = fb + (size_t)(c0 + 4) * cs;
            n0 = __ldg(nb); n1 = __ldg(nb + cs); n2 = __ldg(nb + 2*cs); n3 = __ldg(nb + 3*cs);
        }
        const ulonglong2* w0 = wp + (size_t)c0 * 8;
        u64 xx;
        xx = pk2(x0, x0);
        #pragma unroll
        for (int q = 0; q < 8; ++q) {
            ulonglong2 w = w0[q];
            acc[2*q]   = ffma2(w.x, xx, acc[2*q]);
            acc[2*q+1] = ffma2(w.y, xx, acc[2*q+1]);
        }
        xx = pk2(x1, x1);
        #pragma unroll
        for (int q = 0; q < 8; ++q) {
            ulonglong2 w = w0[8 + q];
            acc[2*q]   = ffma2(w.x, xx, acc[2*q]);
            acc[2*q+1] = ffma2(w.y, xx, acc[2*q+1]);
        }
        xx = pk2(x2, x2);
        #pragma unroll
        for (int q = 0; q < 8; ++q) {
            ulonglong2 w = w0[16 + q];
            acc[2*q]   = ffma2(w.x, xx, acc[2*q]);
            acc[2*q+1] = ffma2(w.y, xx, acc[2*q+1]);
        }
        xx = pk2(x3, x3);
        #pragma unroll
        for (int q = 0; q < 8; ++q) {
            ulonglong2 w = w0[24 + q];
            acc[2*q]   = ffma2(w.x, xx, acc[2*q]);
            acc[2*q+1] = ffma2(w.y, xx, acc[2*q+1]);
        }
        x0 = n0; x1 = n1; x2 = n2; x3 = n3;
    }

    // tanh (HW approx) + fold into a2
    #pragma unroll
    for (int j = 0; j < 16; ++j) {
        float ha, hb; upk2(acc[j], ha, hb);
        ha = tanha(ha); hb = tanha(hb);
        const u64 xa = pk2(ha, ha);
        const u64 xb = pk2(hb, hb);
        const ulonglong2* ma = sMf[2*j];
        const ulonglong2* mb = sMf[2*j + 1];
        #pragma unroll
        for (int q = 0; q < 8; ++q) {
            ulonglong2 wA = ma[q];
            a2[2*q]   = ffma2(wA.x, xa, a2[2*q]);
            a2[2*q+1] = ffma2(wA.y, xa, a2[2*q+1]);
        }
        #pragma unroll
        for (int q = 0; q < 8; ++q) {
            ulonglong2 wB = mb[q];
            a2[2*q]   = ffma2(wB.x, xb, a2[2*q]);
            a2[2*q+1] = ffma2(wB.y, xb, a2[2*q+1]);
        }
    }
}

// ---------------- main fused kernel ----------------
// 256 threads = 4 groups of 64; each group = one (b,p), one thread per anchor.
// Force 2 blocks/SM (<=128 regs) — round-1 profile showed occupancy-capped.
__global__ void __launch_bounds__(256, 2) disarm_main(
    const float* __restrict__ loc, const float* __restrict__ feat,
    float* __restrict__ out)
{
    __shared__ ulonglong2 sW[2][FDc][8];  // 32 KB : layer-1 pairs, pass-major
    __shared__ ulonglong2 sMf[64][8];     //  8 KB
    __shared__ ulonglong2 sMs[16][8];     //  2 KB
    __shared__ float sc1[64], sca[32], sWa2v[32];
    __shared__ float sB1[8][4], sd1[8], sB2[16][8], sd2[16];
    __shared__ float sba2;
    __shared__ float rmx[4][2], rmn[4][2], rsum[4][2];

    const int tid = threadIdx.x;

    // stage folded weights into shared
    {
        u64* d = (u64*)&sW[0][0][0]; const u64* s = &g_W[0][0][0];
        for (int i = tid; i < 2*FDc*16; i += 256) d[i] = s[i];
        u64* d2 = (u64*)&sMf[0][0]; const u64* s2 = &g_Mf[0][0];
        for (int i = tid; i < 64*16; i += 256) d2[i] = s2[i];
        u64* d3 = (u64*)&sMs[0][0]; const u64* s3 = &g_Ms[0][0];
        d3[tid] = s3[tid];
        if (tid < 64) sc1[tid] = g_c1[tid];
        if (tid < 32) { sca[tid] = g_ca[tid]; sWa2v[tid] = g_Wa2[tid]; }
        if (tid < 32) sB1[tid>>2][tid&3] = g_B1[tid>>2][tid&3];
        if (tid < 8)  sd1[tid] = g_d1[tid];
        if (tid < 128) sB2[tid>>3][tid&7] = g_B2[tid>>3][tid&7];
        if (tid < 16) sd2[tid] = g_d2[tid];
        if (tid == 0) sba2 = g_ba2s;
    }
    __syncthreads();

    const int grp = tid >> 6;
    const int gt  = tid & 63;           // anchor index
    const int gp  = blockIdx.x * 4 + grp;
    const int b   = gp >> 10;
    const int p   = gp & 1023;

    // ---- spatial branch: 3 -> 8 -> 16 (HW tanh) ----
    const float* lp = loc + (((size_t)(b*NUMc + p))*NAc + gt) * 3;
    const float l0 = lp[0], l1 = lp[1], l2 = lp[2];
    float s1v[8];
    #pragma unroll
    for (int j = 0; j < 8; ++j)
        s1v[j] = tanha(sB1[j][0]*l0 + sB1[j][1]*l1 + sB1[j][2]*l2 + sd1[j]);
    float s2v[16];
    #pragma unroll
    for (int j = 0; j < 16; ++j) {
        float a = sd2[j];
        #pragma unroll
        for (int i = 0; i < 8; ++i) a += sB2[j][i] * s1v[i];
        s2v[j] = tanha(a);
    }

    // ---- a2 = ca + Ms@s2  (spatial contribution first, frees s2v) ----
    u64 a2[16];
    #pragma unroll
    for (int q = 0; q < 16; ++q) a2[q] = pk2(sca[2*q], sca[2*q+1]);
    #pragma unroll
    for (int n = 0; n < 16; ++n) {
        u64 xx = pk2(s2v[n], s2v[n]);
        #pragma unroll
        for (int q2 = 0; q2 < 8; ++q2) {
            ulonglong2 w = sMs[n][q2];
            a2[2*q2]   = ffma2(w.x, xx, a2[2*q2]);
            a2[2*q2+1] = ffma2(w.y, xx, a2[2*q2+1]);
        }
    }

    // ---- feature branch: two 32-output passes over the 128 channels ----
    const size_t cs = (size_t)NUMc * NAc;
    const float* fb = feat + (size_t)b * FDc * cs + (size_t)p * NAc + gt;

    half_pass(&sW[0][0][0], &sMf[0],  sc1,      fb, cs, a2);
    half_pass(&sW[1][0][0], &sMf[32], sc1 + 32, fb, cs, a2);

    // ---- scalar head (precise tanhf — min-max norm amplifies logit noise) ----
    float outv = sba2;
    #pragma unroll
    for (int q = 0; q < 16; ++q) {
        float a, bb; upk2(a2[q], a, bb);
        outv += sWa2v[2*q] * tanhf(a) + sWa2v[2*q+1] * tanhf(bb);
    }
    const float lg = tanhf(outv);

    // ---- softmax over 64 anchors + min-max norm ----
    const unsigned m32 = 0xffffffffu;
    float mx = lg, mn = lg;
    #pragma unroll
    for (int off = 16; off > 0; off >>= 1) {
        mx = fmaxf(mx, __shfl_xor_sync(m32, mx, off));
        mn = fminf(mn, __shfl_xor_sync(m32, mn, off));
    }
    const int half = gt >> 5;
    if ((gt & 31) == 0) { rmx[grp][half] = mx; rmn[grp][half] = mn; }
    __syncthreads();
    mx = fmaxf(rmx[grp][0], rmx[grp][1]);
    mn = fminf(rmn[grp][0], rmn[grp][1]);

    const float e = expf(lg - mx);
    float s = e;
    #pragma unroll
    for (int off = 16; off > 0; off >>= 1) s += __shfl_xor_sync(m32, s, off);
    if ((gt & 31) == 0) rsum[grp][half] = s;
    __syncthreads();
    const float sum  = rsum[grp][0] + rsum[grp][1];
    const float invs = 1.0f / sum;

    const float w   = e * invs;
    const float wmn = expf(mn - mx) * invs;
    const float wmx = invs;
    const float k   = (1.0f + 1e-6f) / (wmx - wmn + 1e-6f);
    const float wn  = k * (w - wmn);

    const size_t oi = (size_t)gp * NAc + gt;
    out[oi] = w;
    out[(size_t)BZc * NUMc * NAc + oi] = wn;
}

// ---------------- launch ----------------
extern "C" void kernel_launch(void* const* d_in, const int* in_sizes, int n_in,
                              void* d_out, int out_size)
{
    const float* loc  = (const float*)d_in[0];
    const float* feat = (const float*)d_in[1];

    disarm_prep<<<1, 256>>>(
        (const float*)d_in[2],  (const float*)d_in[3],  (const float*)d_in[4],  (const float*)d_in[5],
        (const float*)d_in[6],  (const float*)d_in[7],
        (const float*)d_in[8],  (const float*)d_in[9],  (const float*)d_in[10], (const float*)d_in[11],
        (const float*)d_in[12], (const float*)d_in[13], (const float*)d_in[14], (const float*)d_in[15],
        (const float*)d_in[16], (const float*)d_in[17],
        (const float*)d_in[18], (const float*)d_in[19], (const float*)d_in[20], (const float*)d_in[21],
        (const float*)d_in[22], (const float*)d_in[23]);

    disarm_main<<<(BZc * NUMc) / 4, 256>>>(loc, feat, (float*)d_out);
}

// round 3
// speedup vs baseline: 1.4958x; 1.2684x over previous
#include <cuda_runtime.h>

// Problem dims
#define BZc   8
#define NUMc  1024
#define NAc   64
#define FDc   128

typedef unsigned long long u64;

// ---------------- packed f32x2 helpers (sm_100+ PTX) ----------------
__device__ __forceinline__ u64 pk2(float a, float b) {
    u64 r; asm("mov.b64 %0, {%1,%2};" : "=l"(r) : "f"(a), "f"(b)); return r;
}
__device__ __forceinline__ void upk2(u64 v, float& a, float& b) {
    asm("mov.b64 {%0,%1}, %2;" : "=f"(a), "=f"(b) : "l"(v));
}
__device__ __forceinline__ u64 ffma2(u64 a, u64 b, u64 c) {
    u64 d; asm("fma.rn.f32x2 %0, %1, %2, %3;" : "=l"(d) : "l"(a), "l"(b), "l"(c)); return d;
}
// HW tanh approx (1 MUFU op) — hidden activations only.
__device__ __forceinline__ float tanha(float x) {
    float y; asm("tanh.approx.f32 %0, %1;" : "=f"(y) : "f"(x)); return y;
}

// ---------------- folded weight storage (device globals) ----------------
// Layer-1 weights, quarter-pass major: pass q covers outputs [16q, 16q+16).
// g_W[q][c][j] packs outputs (16q+2j, 16q+2j+1) for channel c.
__device__ u64   g_W[4][FDc][8];
__device__ float g_c1[64];
__device__ u64   g_Mf[64][16];    // folded (ga/s)*Wa1_f@Wf2, pairs over agg o
__device__ u64   g_Ms[16][16];    // folded (ga/s)*Wa1_s@Ws3, pairs over agg o
__device__ float g_ca[32];
__device__ float g_B1[8][4];
__device__ float g_d1[8];
__device__ float g_B2[16][8];
__device__ float g_d2[16];
__device__ float g_Wa2[32];
__device__ float g_ba2s;

// ---------------- weight folding kernel ----------------
__global__ void disarm_prep(
    const float* __restrict__ Wf1, const float* __restrict__ bf1,
    const float* __restrict__ gf1, const float* __restrict__ btf1,
    const float* __restrict__ Wf2, const float* __restrict__ bf2,
    const float* __restrict__ Ws1, const float* __restrict__ bs1,
    const float* __restrict__ gs1, const float* __restrict__ bts1,
    const float* __restrict__ Ws2, const float* __restrict__ bs2,
    const float* __restrict__ gs2, const float* __restrict__ bts2,
    const float* __restrict__ Ws3, const float* __restrict__ bs3,
    const float* __restrict__ Wa1, const float* __restrict__ ba1,
    const float* __restrict__ ga1, const float* __restrict__ bta1,
    const float* __restrict__ Wa2, const float* __restrict__ ba2)
{
    const float inv = rsqrtf(1.0f + 1e-5f);
    const int t = threadIdx.x;
    const int nt = blockDim.x;

    // Layer-1 pairs, quarter-pass major
    for (int i = t; i < 4 * FDc * 8; i += nt) {
        int q = i / (FDc * 8);
        int c = (i >> 3) & (FDc - 1);
        int j = i & 7;
        int o0 = 16 * q + 2 * j;
        float a = gf1[o0]   * inv * Wf1[o0 * FDc + c];
        float b = gf1[o0+1] * inv * Wf1[(o0+1) * FDc + c];
        g_W[q][c][j] = pk2(a, b);
    }
    for (int i = t; i < 64; i += nt) g_c1[i] = gf1[i]*inv*bf1[i] + btf1[i];

    // Mf[h][q]: o = 2q, 2q+1 : ga1[o]*inv * sum_k Wa1[o][32+k]*Wf2[k][h]
    for (int i = t; i < 64 * 16; i += nt) {
        int h = i >> 4, q = i & 15;
        float v[2];
        #pragma unroll
        for (int s = 0; s < 2; ++s) {
            int o = 2*q + s;
            float acc = 0.0f;
            for (int k = 0; k < 32; ++k) acc += Wa1[o*64 + 32 + k] * Wf2[k*64 + h];
            v[s] = ga1[o] * inv * acc;
        }
        g_Mf[h][q] = pk2(v[0], v[1]);
    }
    // Ms[n][q]
    for (int i = t; i < 16 * 16; i += nt) {
        int n = i >> 4, q = i & 15;
        float v[2];
        #pragma unroll
        for (int s = 0; s < 2; ++s) {
            int o = 2*q + s;
            float acc = 0.0f;
            for (int m = 0; m < 32; ++m) acc += Wa1[o*64 + m] * Ws3[m*16 + n];
            v[s] = ga1[o] * inv * acc;
        }
        g_Ms[n][q] = pk2(v[0], v[1]);
    }
    if (t < 32) {
        float acc = 0.0f;
        for (int k = 0; k < 32; ++k) acc += Wa1[t*64 + 32 + k] * bf2[k];
        for (int m = 0; m < 32; ++m) acc += Wa1[t*64 + m] * bs3[m];
        g_ca[t] = ga1[t]*inv*(acc + ba1[t]) + bta1[t];
    }
    if (t < 8) {
        for (int i = 0; i < 3; ++i) g_B1[t][i] = gs1[t]*inv*Ws1[t*3 + i];
        g_B1[t][3] = 0.0f;
        g_d1[t] = gs1[t]*inv*bs1[t] + bts1[t];
    }
    if (t < 16) {
        for (int i = 0; i < 8; ++i) g_B2[t][i] = gs2[t]*inv*Ws2[t*8 + i];
        g_d2[t] = gs2[t]*inv*bs2[t] + bts2[t];
    }
    if (t < 32) g_Wa2[t] = Wa2[t];
    if (t == 0) g_ba2s = ba2[0];
}

// ---------------- main fused kernel ----------------
// 256 threads = 8 warps; each warp owns one (b,p) group; each lane owns
// anchors (2*lane, 2*lane+1). Two anchor accumulator sets share every weight
// load: one LDS.128 feeds 4 ffma2 (fixes round-2 L1TEX wavefront bound).
__global__ void __launch_bounds__(256, 2) disarm_main(
    const float* __restrict__ loc, const float* __restrict__ feat,
    float* __restrict__ out)
{
    __shared__ ulonglong2 sW[4][FDc][4];  // 32 KB : quarter-pass weight pairs
    __shared__ ulonglong2 sMf[64][8];     //  8 KB
    __shared__ ulonglong2 sMs[16][8];     //  2 KB
    __shared__ float sc1[64], sca[32], sWa2v[32];
    __shared__ float sB1[8][4], sd1[8], sB2[16][8], sd2[16];
    __shared__ float sba2;

    const int tid = threadIdx.x;

    // stage folded weights into shared
    {
        u64* d = (u64*)&sW[0][0][0]; const u64* s = &g_W[0][0][0];
        for (int i = tid; i < 4*FDc*8; i += 256) d[i] = s[i];
        u64* d2 = (u64*)&sMf[0][0]; const u64* s2 = &g_Mf[0][0];
        for (int i = tid; i < 64*16; i += 256) d2[i] = s2[i];
        u64* d3 = (u64*)&sMs[0][0]; const u64* s3 = &g_Ms[0][0];
        d3[tid] = s3[tid];
        if (tid < 64) sc1[tid] = g_c1[tid];
        if (tid < 32) { sca[tid] = g_ca[tid]; sWa2v[tid] = g_Wa2[tid]; }
        if (tid < 32) sB1[tid>>2][tid&3] = g_B1[tid>>2][tid&3];
        if (tid < 8)  sd1[tid] = g_d1[tid];
        if (tid < 128) sB2[tid>>3][tid&7] = g_B2[tid>>3][tid&7];
        if (tid < 16) sd2[tid] = g_d2[tid];
        if (tid == 0) sba2 = g_ba2s;
    }
    __syncthreads();

    const int warp = tid >> 5;
    const int lane = tid & 31;
    const int gp   = blockIdx.x * 8 + warp;
    const int b    = gp >> 10;
    const int p    = gp & 1023;
    const int a0   = 2 * lane;            // first of this lane's two anchors

    // ---- persistent aggregated pre-activation: a2[anchor][o-pair] ----
    u64 a2[2][16];
    #pragma unroll
    for (int q = 0; q < 16; ++q) {
        u64 init = pk2(sca[2*q], sca[2*q+1]);
        a2[0][q] = init; a2[1][q] = init;
    }

    // ---- spatial branch per anchor, folded into a2 immediately ----
    {
        const float* lp = loc + (((size_t)(b*NUMc + p))*NAc + a0) * 3;
        #pragma unroll
        for (int s = 0; s < 2; ++s) {
            const float l0 = lp[3*s], l1 = lp[3*s+1], l2 = lp[3*s+2];
            float s1v[8];
            #pragma unroll
            for (int j = 0; j < 8; ++j)
                s1v[j] = tanha(sB1[j][0]*l0 + sB1[j][1]*l1 + sB1[j][2]*l2 + sd1[j]);
            #pragma unroll
            for (int n = 0; n < 16; ++n) {
                float a = sd2[n];
                #pragma unroll
                for (int i = 0; i < 8; ++i) a += sB2[n][i] * s1v[i];
                const float t2 = tanha(a);
                const u64 xx = pk2(t2, t2);
                #pragma unroll
                for (int q2 = 0; q2 < 8; ++q2) {
                    ulonglong2 w = sMs[n][q2];
                    a2[s][2*q2]   = ffma2(w.x, xx, a2[s][2*q2]);
                    a2[s][2*q2+1] = ffma2(w.y, xx, a2[s][2*q2+1]);
                }
            }
        }
    }

    // ---- feature branch: four 16-output quarter-passes over 128 channels ----
    const size_t cs = (size_t)NUMc * NAc;   // 65536
    const float2* fb = (const float2*)(feat + (size_t)b * FDc * cs + (size_t)p * NAc + a0);
    const size_t cs2 = cs >> 1;             // float2 stride per channel

    #pragma unroll
    for (int pass = 0; pass < 4; ++pass) {
        u64 acc[2][8];
        #pragma unroll
        for (int j = 0; j < 8; ++j) {
            u64 init = pk2(sc1[16*pass + 2*j], sc1[16*pass + 2*j + 1]);
            acc[0][j] = init; acc[1][j] = init;
        }

        // channel loop, 2-wide with 1-deep prefetch
        float2 x0 = __ldg(fb);
        float2 x1 = __ldg(fb + cs2);
        for (int c0 = 0; c0 < FDc; c0 += 2) {
            float2 n0, n1;
            if (c0 + 2 < FDc) {
                n0 = __ldg(fb + (size_t)(c0 + 2) * cs2);
                n1 = __ldg(fb + (size_t)(c0 + 3) * cs2);
            } else { n0 = make_float2(0.f,0.f); n1 = n0; }

            {
                const u64 xa = pk2(x0.x, x0.x);
                const u64 xb = pk2(x0.y, x0.y);
                const ulonglong2* w0 = &sW[pass][c0][0];
                #pragma unroll
                for (int q = 0; q < 4; ++q) {
                    ulonglong2 w = w0[q];
                    acc[0][2*q]   = ffma2(w.x, xa, acc[0][2*q]);
                    acc[0][2*q+1] = ffma2(w.y, xa, acc[0][2*q+1]);
                    acc[1][2*q]   = ffma2(w.x, xb, acc[1][2*q]);
                    acc[1][2*q+1] = ffma2(w.y, xb, acc[1][2*q+1]);
                }
            }
            {
                const u64 xa = pk2(x1.x, x1.x);
                const u64 xb = pk2(x1.y, x1.y);
                const ulonglong2* w1 = &sW[pass][c0+1][0];
                #pragma unroll
                for (int q = 0; q < 4; ++q) {
                    ulonglong2 w = w1[q];
                    acc[0][2*q]   = ffma2(w.x, xa, acc[0][2*q]);
                    acc[0][2*q+1] = ffma2(w.y, xa, acc[0][2*q+1]);
                    acc[1][2*q]   = ffma2(w.x, xb, acc[1][2*q]);
                    acc[1][2*q+1] = ffma2(w.y, xb, acc[1][2*q+1]);
                }
            }
            x0 = n0; x1 = n1;
        }

        // tanh + fold this pass's 16 hidden units into a2 (Mf rows shared
        // across both anchors: 8 LDS.128 -> 32 ffma2)
        #pragma unroll
        for (int j = 0; j < 8; ++j) {
            float ha0, ha1, hb0, hb1;
            upk2(acc[0][j], ha0, ha1);
            upk2(acc[1][j], hb0, hb1);
            ha0 = tanha(ha0); ha1 = tanha(ha1);
            hb0 = tanha(hb0); hb1 = tanha(hb1);

            const ulonglong2* r0 = sMf[16*pass + 2*j];
            const ulonglong2* r1 = sMf[16*pass + 2*j + 1];
            {
                const u64 xa = pk2(ha0, ha0);
                const u64 xb = pk2(hb0, hb0);
                #pragma unroll
                for (int q2 = 0; q2 < 8; ++q2) {
                    ulonglong2 w = r0[q2];
                    a2[0][2*q2]   = ffma2(w.x, xa, a2[0][2*q2]);
                    a2[0][2*q2+1] = ffma2(w.y, xa, a2[0][2*q2+1]);
                    a2[1][2*q2]   = ffma2(w.x, xb, a2[1][2*q2]);
                    a2[1][2*q2+1] = ffma2(w.y, xb, a2[1][2*q2+1]);
                }
            }
            {
                const u64 xa = pk2(ha1, ha1);
                const u64 xb = pk2(hb1, hb1);
                #pragma unroll
                for (int q2 = 0; q2 < 8; ++q2) {
                    ulonglong2 w = r1[q2];
                    a2[0][2*q2]   = ffma2(w.x, xa, a2[0][2*q2]);
                    a2[0][2*q2+1] = ffma2(w.y, xa, a2[0][2*q2+1]);
                    a2[1][2*q2]   = ffma2(w.x, xb, a2[1][2*q2]);
                    a2[1][2*q2+1] = ffma2(w.y, xb, a2[1][2*q2+1]);
                }
            }
        }
    }

    // ---- scalar head per anchor (precise tanhf: min-max amplifies noise) ----
    float lg[2];
    #pragma unroll
    for (int s = 0; s < 2; ++s) {
        float outv = sba2;
        #pragma unroll
        for (int q = 0; q < 16; ++q) {
            float a, bb; upk2(a2[s][q], a, bb);
            outv += sWa2v[2*q] * tanhf(a) + sWa2v[2*q+1] * tanhf(bb);
        }
        lg[s] = tanhf(outv);
    }

    // ---- softmax over 64 anchors (pure warp shuffles) + min-max norm ----
    const unsigned m32 = 0xffffffffu;
    float mx = fmaxf(lg[0], lg[1]);
    float mn = fminf(lg[0], lg[1]);
    #pragma unroll
    for (int off = 16; off > 0; off >>= 1) {
        mx = fmaxf(mx, __shfl_xor_sync(m32, mx, off));
        mn = fminf(mn, __shfl_xor_sync(m32, mn, off));
    }
    const float e0 = expf(lg[0] - mx);
    const float e1 = expf(lg[1] - mx);
    float s = e0 + e1;
    #pragma unroll
    for (int off = 16; off > 0; off >>= 1) s += __shfl_xor_sync(m32, s, off);
    const float invs = 1.0f / s;

    const float w0  = e0 * invs;
    const float w1  = e1 * invs;
    const float wmn = expf(mn - mx) * invs;  // min over anchors of w
    const float wmx = invs;                  // max: exp(0)/sum
    const float k   = (1.0f + 1e-6f) / (wmx - wmn + 1e-6f);

    float2* o0 = (float2*)(out + (size_t)gp * NAc + a0);
    float2* o1 = (float2*)(out + (size_t)BZc * NUMc * NAc + (size_t)gp * NAc + a0);
    *o0 = make_float2(w0, w1);
    *o1 = make_float2(k * (w0 - wmn), k * (w1 - wmn));
}

// ---------------- launch ----------------
extern "C" void kernel_launch(void* const* d_in, const int* in_sizes, int n_in,
                              void* d_out, int out_size)
{
    const float* loc  = (const float*)d_in[0];
    const float* feat = (const float*)d_in[1];

    disarm_prep<<<1, 256>>>(
        (const float*)d_in[2],  (const float*)d_in[3],  (const float*)d_in[4],  (const float*)d_in[5],
        (const float*)d_in[6],  (const float*)d_in[7],
        (const float*)d_in[8],  (const float*)d_in[9],  (const float*)d_in[10], (const float*)d_in[11],
        (const float*)d_in[12], (const float*)d_in[13], (const float*)d_in[14], (const float*)d_in[15],
        (const float*)d_in[16], (const float*)d_in[17],
        (const float*)d_in[18], (const float*)d_in[19], (const float*)d_in[20], (const float*)d_in[21],
        (const float*)d_in[22], (const float*)d_in[23]);

    disarm_main<<<(BZc * NUMc) / 8, 256>>>(loc, feat, (float*)d_out);
}